// round 7
// baseline (speedup 1.0000x reference)
#include <cuda_runtime.h>
#include <cuda_bf16.h>
#include <math_constants.h>

// Problem constants (fixed shapes)
#define BB 64
#define LL 512
#define HH 768
#define TT 9
#define NROWS (BB * LL)

#define NCH 8        // chunks per sequence
#define CHLEN 64     // steps per chunk

__device__ float g_llh[BB];
__device__ float g_logits_scratch[BB * LL * TT];   // fallback if out has no room

// ---------------------------------------------------------------------------
// Kernel A: logits = hidden @ W + b
// Warp computes 2 consecutive rows; lane = K dim (coalesced LDG.128).
// Rolling 2-stage load pipeline (4 LDG in flight, not 12) + launch_bounds
// (256,2) to guarantee 2 CTAs/SM (16 warps).
// W in smem, swizzled Ws[9k + t + (k>>5)]: bank = (4*(lane&7) + (lane>>3))
// + const -> all 32 lanes distinct -> conflict-free scalar LDS.
// ---------------------------------------------------------------------------
__global__ __launch_bounds__(256, 2) void logits_kernel(
    const float* __restrict__ hidden,
    const float* __restrict__ W,
    const float* __restrict__ bias,
    float* __restrict__ logits)
{
    __shared__ float Ws[HH * TT + (HH >> 5)];   // 6936 floats
    __shared__ float bs[TT];

    for (int i = threadIdx.x; i < HH * TT; i += 256) {
        int k = i / 9;
        int t = i - 9 * k;
        Ws[9 * k + t + (k >> 5)] = W[i];
    }
    if (threadIdx.x < TT) bs[threadIdx.x] = bias[threadIdx.x];
    __syncthreads();

    const int lane = threadIdx.x & 31;
    const int gw   = blockIdx.x * 8 + (threadIdx.x >> 5);   // 0..8191

    #pragma unroll
    for (int half = 0; half < 2; half++) {
        const int rp = gw + half * 8192;        // row pair id, 0..16383
        const float4* h0 = (const float4*)(hidden + (size_t)(2 * rp) * HH);
        const float4* h1 = h0 + (HH / 4);

        float acc0[TT], acc1[TT];
        #pragma unroll
        for (int t = 0; t < TT; t++) { acc0[t] = 0.f; acc1[t] = 0.f; }

        // rolling 2-stage pipeline: cur compute, nxt loading
        float4 c0 = h0[lane];
        float4 c1 = h1[lane];

        #pragma unroll
        for (int it = 0; it < 6; it++) {
            float4 n0, n1;
            if (it < 5) {
                n0 = h0[(it + 1) * 32 + lane];
                n1 = h1[(it + 1) * 32 + lane];
            }

            const int k4 = it * 32 + lane;
            const int wb = 36 * k4 + (k4 >> 3);
            const float hx0[4] = {c0.x, c0.y, c0.z, c0.w};
            const float hx1[4] = {c1.x, c1.y, c1.z, c1.w};
            #pragma unroll
            for (int kk = 0; kk < 4; kk++) {
                const float* wr = &Ws[wb + 9 * kk];
                const float h0v = hx0[kk];
                const float h1v = hx1[kk];
                #pragma unroll
                for (int t = 0; t < TT; t++) {
                    const float w = wr[t];
                    acc0[t] = fmaf(h0v, w, acc0[t]);
                    acc1[t] = fmaf(h1v, w, acc1[t]);
                }
            }

            c0 = n0;
            c1 = n1;
        }

        // butterfly: every lane ends with the full sums
        #pragma unroll
        for (int t = 0; t < TT; t++) {
            #pragma unroll
            for (int off = 16; off > 0; off >>= 1) {
                acc0[t] += __shfl_xor_sync(0xffffffffu, acc0[t], off);
                acc1[t] += __shfl_xor_sync(0xffffffffu, acc1[t], off);
            }
        }

        float* o = logits + (size_t)(2 * rp) * TT;
        #pragma unroll
        for (int t = 0; t < TT; t++) {
            if (lane == t)      o[t]      = acc0[t] + bs[t];
            if (lane == 9 + t)  o[TT + t] = acc1[t] + bs[t];
        }
    }
}

// ---------------------------------------------------------------------------
// Kernel B: per-batch CRF with CHUNKED parallel scan (unchanged — working).
// ---------------------------------------------------------------------------
__global__ __launch_bounds__(800) void crf_kernel(
    const float* __restrict__ logits,
    const int*   __restrict__ mask,
    const int*   __restrict__ labels,
    const float* __restrict__ start_trans,
    const float* __restrict__ end_trans,
    const float* __restrict__ trans)
{
    __shared__ float e_s[LL * TT];
    __shared__ float ee_s[LL * TT];
    __shared__ float m_s[LL];
    __shared__ int   lab_s[LL];
    __shared__ float tr_s[TT * TT];
    __shared__ float st_s[TT];
    __shared__ float en_s[TT];
    __shared__ float M_s[NCH * TT * TT];
    __shared__ float E_s[NCH * TT];
    __shared__ float num_sh;

    const int b    = blockIdx.x;
    const int tid  = threadIdx.x;
    const int lane = tid & 31;
    const int warp = tid >> 5;

    const float L2E = 1.4426950408889634f;
    const float LN2 = 0.6931471805599453f;

    const float* lg = logits + (size_t)b * LL * TT;
    #pragma unroll 2
    for (int i = tid; i < LL * TT; i += 800) {
        float e = lg[i];
        e_s[i]  = e;
        ee_s[i] = exp2f(e * L2E);
    }
    for (int i = tid; i < LL; i += 800) {
        int l = labels[(size_t)b * LL + i];
        lab_s[i] = (l == -100) ? 0 : l;
        m_s[i]   = (float)mask[(size_t)b * LL + i];
    }
    if (tid < TT * TT) tr_s[tid] = trans[tid];
    if (tid < TT) { st_s[tid] = start_trans[tid]; en_s[tid] = end_trans[tid]; }
    __syncthreads();

    if (warp < 24) {
        const int c  = warp / 3;
        const int rg = warp % 3;
        int r = lane / 9; if (r > 2) r = 2;
        const int j = lane % 9;
        const int i = rg * 3 + r;
        const int base = r * 9;

        float et[TT];
        #pragma unroll
        for (int k = 0; k < TT; k++) et[k] = exp2f(tr_s[k * TT + j] * L2E);

        float q = (j == i) ? 1.f : 0.f;
        int   E = 0;

        const int t0 = c * CHLEN + 1;
        int t1 = t0 + CHLEN; if (t1 > LL) t1 = LL;

        float eej_next = ee_s[t0 * TT + j];
        float ms_next  = m_s[t0];

        for (int t = t0; t < t1; t++) {
            const float eej = eej_next;
            const float ms  = ms_next;
            if (t + 1 < t1) {
                eej_next = ee_s[(t + 1) * TT + j];
                ms_next  = m_s[t + 1];
            }

            float p0 = __shfl_sync(0xffffffffu, q, base + 0);
            float p1 = __shfl_sync(0xffffffffu, q, base + 1);
            float p2 = __shfl_sync(0xffffffffu, q, base + 2);
            float p3 = __shfl_sync(0xffffffffu, q, base + 3);
            float p4 = __shfl_sync(0xffffffffu, q, base + 4);
            float p5 = __shfl_sync(0xffffffffu, q, base + 5);
            float p6 = __shfl_sync(0xffffffffu, q, base + 6);
            float p7 = __shfl_sync(0xffffffffu, q, base + 7);
            float p8 = __shfl_sync(0xffffffffu, q, base + 8);

            float a  = fmaf(p1, et[1], p0 * et[0]);  a  = fmaf(p2, et[2], a);
            float b2 = fmaf(p4, et[4], p3 * et[3]);  b2 = fmaf(p5, et[5], b2);
            float cc = fmaf(p7, et[7], p6 * et[6]);  cc = fmaf(p8, et[8], cc);
            float s  = ((a + b2) + cc) * eej;

            q = (ms != 0.f) ? s : q;

            if ((t & 7) == 7) {
                float pm = fmaxf(fmaxf(fmaxf(p0, p1), fmaxf(p2, p3)),
                                 fmaxf(fmaxf(p4, p5), fmaxf(p6, p7)));
                pm = fmaxf(pm, p8);
                int ex = (__float_as_int(pm) >> 23) & 0xFF;
                float sc = __int_as_float((254 - ex) << 23);
                q *= sc;
                E += ex - 127;
            }
        }

        if (lane < 27) {
            M_s[(c * TT + i) * TT + j] = q;
            if (j == 0) E_s[c * TT + i] = (float)E;
        }
    } else {
        float acc = 0.f;
        int   msum = 0;
        for (int t = lane; t < LL; t += 32) {
            msum += (m_s[t] != 0.f) ? 1 : 0;
            if (t >= 1) {
                int lp = lab_s[t - 1], lt = lab_s[t];
                acc = fmaf(tr_s[lp * TT + lt] + e_s[t * TT + lt], m_s[t], acc);
            }
        }
        #pragma unroll
        for (int off = 16; off > 0; off >>= 1) {
            acc  += __shfl_xor_sync(0xffffffffu, acc, off);
            msum += __shfl_xor_sync(0xffffffffu, msum, off);
        }
        if (lane == 0) {
            int seq_end = msum - 1;
            if (seq_end < 0) seq_end = 0;
            int l0 = lab_s[0];
            int llast = lab_s[seq_end];
            num_sh = st_s[l0] + e_s[l0] + acc + en_s[llast];
        }
    }

    __syncthreads();

    if (warp == 0) {
        const int j = (lane < TT) ? lane : (TT - 1);

        float q  = exp2f((st_s[j] + e_s[j]) * L2E);
        int   Eq = 0;

        for (int c = 0; c < NCH; c++) {
            float Ek[TT];
            #pragma unroll
            for (int k = 0; k < TT; k++) Ek[k] = E_s[c * TT + k];
            float Em = Ek[0];
            #pragma unroll
            for (int k = 1; k < TT; k++) Em = fmaxf(Em, Ek[k]);

            float s = 0.f;
            #pragma unroll
            for (int k = 0; k < TT; k++) {
                float pk = __shfl_sync(0xffffffffu, q, k);
                float d  = Ek[k] - Em;
                float sc = (d > -120.f)
                         ? __int_as_float((((int)d) + 127) << 23) : 0.f;
                s = fmaf(pk * sc, M_s[(c * TT + k) * TT + j], s);
            }
            q  = s;
            Eq += (int)Em;

            float q0 = __shfl_sync(0xffffffffu, q, 0);
            float q1 = __shfl_sync(0xffffffffu, q, 1);
            float q2 = __shfl_sync(0xffffffffu, q, 2);
            float q3 = __shfl_sync(0xffffffffu, q, 3);
            float q4 = __shfl_sync(0xffffffffu, q, 4);
            float q5 = __shfl_sync(0xffffffffu, q, 5);
            float q6 = __shfl_sync(0xffffffffu, q, 6);
            float q7 = __shfl_sync(0xffffffffu, q, 7);
            float q8 = __shfl_sync(0xffffffffu, q, 8);
            float qm = fmaxf(fmaxf(fmaxf(q0, q1), fmaxf(q2, q3)),
                             fmaxf(fmaxf(q4, q5), fmaxf(q6, q7)));
            qm = fmaxf(qm, q8);
            int ex = (__float_as_int(qm) >> 23) & 0xFF;
            float sc2 = __int_as_float((254 - ex) << 23);
            q  *= sc2;
            Eq += ex - 127;
        }

        float v = (lane < TT) ? q * exp2f(en_s[j] * L2E) : 0.f;
        #pragma unroll
        for (int off = 16; off > 0; off >>= 1)
            v += __shfl_xor_sync(0xffffffffu, v, off);
        float denom = LN2 * (__log2f(v) + (float)Eq);

        if (lane == 0) g_llh[b] = num_sh - denom;
    }
}

// ---------------------------------------------------------------------------
// Kernel C: loss = -mean(llh), deterministic tree reduce
// ---------------------------------------------------------------------------
__global__ void loss_kernel(float* __restrict__ loss_out)
{
    int lane = threadIdx.x;   // 32 threads
    float v = g_llh[lane] + g_llh[lane + 32];
    #pragma unroll
    for (int off = 16; off > 0; off >>= 1)
        v += __shfl_xor_sync(0xffffffffu, v, off);
    if (lane == 0) loss_out[0] = -v * (1.0f / (float)BB);
}

// ---------------------------------------------------------------------------
extern "C" void kernel_launch(void* const* d_in, const int* in_sizes, int n_in,
                              void* d_out, int out_size)
{
    const float* hidden      = (const float*)d_in[0];
    const int*   attn_mask   = (const int*)d_in[1];
    const int*   labels      = (const int*)d_in[2];   // int32 (JAX x64 disabled)
    const float* W           = (const float*)d_in[3];
    const float* bias        = (const float*)d_in[4];
    const float* start_trans = (const float*)d_in[5];
    const float* end_trans   = (const float*)d_in[6];
    const float* trans       = (const float*)d_in[7];

    float* out = (float*)d_out;

    static float* scratch = nullptr;
    if (!scratch) {
        void* p = nullptr;
        cudaGetSymbolAddress(&p, g_logits_scratch);
        scratch = (float*)p;
    }

    const int NLOG = BB * LL * TT;   // 294912
    float* loss_ptr;
    float* logits_ptr;
    if (out_size >= NLOG + 1) {          // (loss, logits) concatenated
        loss_ptr   = out;
        logits_ptr = out + 1;
    } else if (out_size == NLOG) {       // logits only
        loss_ptr   = scratch;
        logits_ptr = out;
    } else {                             // loss only
        loss_ptr   = out;
        logits_ptr = scratch;
    }

    logits_kernel<<<1024, 256>>>(hidden, W, bias, logits_ptr);
    crf_kernel<<<BB, 800>>>(logits_ptr, attn_mask, labels,
                            start_trans, end_trans, trans);
    loss_kernel<<<1, 32>>>(loss_ptr);
}

// round 8
// speedup vs baseline: 1.5123x; 1.5123x over previous
#include <cuda_runtime.h>
#include <cuda_bf16.h>
#include <math_constants.h>

// Problem constants (fixed shapes)
#define BB 64
#define LL 512
#define HH 768
#define TT 9
#define NROWS (BB * LL)

#define NCH 8        // chunks per sequence
#define CHLEN 64     // steps per chunk

__device__ float g_llh[BB];
__device__ float g_logits_scratch[BB * LL * TT];   // fallback if out has no room

// ---------------------------------------------------------------------------
// Kernel A: logits = hidden @ W + b
// ONE row-pair per warp (grid 2048 x 256 = 16384 warps = all row pairs).
// Full prefetch: all 12 float4 of the pair issued up front (6 KB in flight
// per warp), then 432 FMA + 216 LDS of compute (~1300 cyc) fully covers the
// 577-cyc DRAM latency. launch_bounds(256,2) caps regs at 128 (fits: 48 load
// regs + 18 acc + temps ~ 90).
// W in smem, swizzled Ws[9k + t + (k>>5)] -> conflict-free scalar LDS.
// ---------------------------------------------------------------------------
__global__ __launch_bounds__(256, 2) void logits_kernel(
    const float* __restrict__ hidden,
    const float* __restrict__ W,
    const float* __restrict__ bias,
    float* __restrict__ logits)
{
    __shared__ float Ws[HH * TT + (HH >> 5)];   // 6936 floats
    __shared__ float bs[TT];

    for (int i = threadIdx.x; i < HH * TT; i += 256) {
        int k = i / 9;
        int t = i - 9 * k;
        Ws[9 * k + t + (k >> 5)] = W[i];
    }
    if (threadIdx.x < TT) bs[threadIdx.x] = bias[threadIdx.x];
    __syncthreads();

    const int lane = threadIdx.x & 31;
    const int rp   = blockIdx.x * 8 + (threadIdx.x >> 5);   // row pair 0..16383

    const float4* h0 = (const float4*)(hidden + (size_t)(2 * rp) * HH);
    const float4* h1 = h0 + (HH / 4);

    // full prefetch: 12 LDG.128 in flight
    float4 a0[6], a1[6];
    #pragma unroll
    for (int it = 0; it < 6; it++) {
        a0[it] = h0[it * 32 + lane];
        a1[it] = h1[it * 32 + lane];
    }

    float acc0[TT], acc1[TT];
    #pragma unroll
    for (int t = 0; t < TT; t++) { acc0[t] = 0.f; acc1[t] = 0.f; }

    #pragma unroll
    for (int it = 0; it < 6; it++) {
        const int k4 = it * 32 + lane;
        const int wb = 36 * k4 + (k4 >> 3);
        const float hx0[4] = {a0[it].x, a0[it].y, a0[it].z, a0[it].w};
        const float hx1[4] = {a1[it].x, a1[it].y, a1[it].z, a1[it].w};
        #pragma unroll
        for (int kk = 0; kk < 4; kk++) {
            const float* wr = &Ws[wb + 9 * kk];
            const float h0v = hx0[kk];
            const float h1v = hx1[kk];
            #pragma unroll
            for (int t = 0; t < TT; t++) {
                const float w = wr[t];
                acc0[t] = fmaf(h0v, w, acc0[t]);
                acc1[t] = fmaf(h1v, w, acc1[t]);
            }
        }
    }

    // butterfly: every lane ends with the full sums
    #pragma unroll
    for (int t = 0; t < TT; t++) {
        #pragma unroll
        for (int off = 16; off > 0; off >>= 1) {
            acc0[t] += __shfl_xor_sync(0xffffffffu, acc0[t], off);
            acc1[t] += __shfl_xor_sync(0xffffffffu, acc1[t], off);
        }
    }

    float* o = logits + (size_t)(2 * rp) * TT;
    #pragma unroll
    for (int t = 0; t < TT; t++) {
        if (lane == t)      o[t]      = acc0[t] + bs[t];
        if (lane == 9 + t)  o[TT + t] = acc1[t] + bs[t];
    }
}

// ---------------------------------------------------------------------------
// Kernel B: per-batch CRF with CHUNKED parallel scan (unchanged — working).
// ---------------------------------------------------------------------------
__global__ __launch_bounds__(800) void crf_kernel(
    const float* __restrict__ logits,
    const int*   __restrict__ mask,
    const int*   __restrict__ labels,
    const float* __restrict__ start_trans,
    const float* __restrict__ end_trans,
    const float* __restrict__ trans)
{
    __shared__ float e_s[LL * TT];
    __shared__ float ee_s[LL * TT];
    __shared__ float m_s[LL];
    __shared__ int   lab_s[LL];
    __shared__ float tr_s[TT * TT];
    __shared__ float st_s[TT];
    __shared__ float en_s[TT];
    __shared__ float M_s[NCH * TT * TT];
    __shared__ float E_s[NCH * TT];
    __shared__ float num_sh;

    const int b    = blockIdx.x;
    const int tid  = threadIdx.x;
    const int lane = tid & 31;
    const int warp = tid >> 5;

    const float L2E = 1.4426950408889634f;
    const float LN2 = 0.6931471805599453f;

    const float* lg = logits + (size_t)b * LL * TT;
    #pragma unroll 2
    for (int i = tid; i < LL * TT; i += 800) {
        float e = lg[i];
        e_s[i]  = e;
        ee_s[i] = exp2f(e * L2E);
    }
    for (int i = tid; i < LL; i += 800) {
        int l = labels[(size_t)b * LL + i];
        lab_s[i] = (l == -100) ? 0 : l;
        m_s[i]   = (float)mask[(size_t)b * LL + i];
    }
    if (tid < TT * TT) tr_s[tid] = trans[tid];
    if (tid < TT) { st_s[tid] = start_trans[tid]; en_s[tid] = end_trans[tid]; }
    __syncthreads();

    if (warp < 24) {
        const int c  = warp / 3;
        const int rg = warp % 3;
        int r = lane / 9; if (r > 2) r = 2;
        const int j = lane % 9;
        const int i = rg * 3 + r;
        const int base = r * 9;

        float et[TT];
        #pragma unroll
        for (int k = 0; k < TT; k++) et[k] = exp2f(tr_s[k * TT + j] * L2E);

        float q = (j == i) ? 1.f : 0.f;
        int   E = 0;

        const int t0 = c * CHLEN + 1;
        int t1 = t0 + CHLEN; if (t1 > LL) t1 = LL;

        float eej_next = ee_s[t0 * TT + j];
        float ms_next  = m_s[t0];

        for (int t = t0; t < t1; t++) {
            const float eej = eej_next;
            const float ms  = ms_next;
            if (t + 1 < t1) {
                eej_next = ee_s[(t + 1) * TT + j];
                ms_next  = m_s[t + 1];
            }

            float p0 = __shfl_sync(0xffffffffu, q, base + 0);
            float p1 = __shfl_sync(0xffffffffu, q, base + 1);
            float p2 = __shfl_sync(0xffffffffu, q, base + 2);
            float p3 = __shfl_sync(0xffffffffu, q, base + 3);
            float p4 = __shfl_sync(0xffffffffu, q, base + 4);
            float p5 = __shfl_sync(0xffffffffu, q, base + 5);
            float p6 = __shfl_sync(0xffffffffu, q, base + 6);
            float p7 = __shfl_sync(0xffffffffu, q, base + 7);
            float p8 = __shfl_sync(0xffffffffu, q, base + 8);

            float a  = fmaf(p1, et[1], p0 * et[0]);  a  = fmaf(p2, et[2], a);
            float b2 = fmaf(p4, et[4], p3 * et[3]);  b2 = fmaf(p5, et[5], b2);
            float cc = fmaf(p7, et[7], p6 * et[6]);  cc = fmaf(p8, et[8], cc);
            float s  = ((a + b2) + cc) * eej;

            q = (ms != 0.f) ? s : q;

            if ((t & 7) == 7) {
                float pm = fmaxf(fmaxf(fmaxf(p0, p1), fmaxf(p2, p3)),
                                 fmaxf(fmaxf(p4, p5), fmaxf(p6, p7)));
                pm = fmaxf(pm, p8);
                int ex = (__float_as_int(pm) >> 23) & 0xFF;
                float sc = __int_as_float((254 - ex) << 23);
                q *= sc;
                E += ex - 127;
            }
        }

        if (lane < 27) {
            M_s[(c * TT + i) * TT + j] = q;
            if (j == 0) E_s[c * TT + i] = (float)E;
        }
    } else {
        float acc = 0.f;
        int   msum = 0;
        for (int t = lane; t < LL; t += 32) {
            msum += (m_s[t] != 0.f) ? 1 : 0;
            if (t >= 1) {
                int lp = lab_s[t - 1], lt = lab_s[t];
                acc = fmaf(tr_s[lp * TT + lt] + e_s[t * TT + lt], m_s[t], acc);
            }
        }
        #pragma unroll
        for (int off = 16; off > 0; off >>= 1) {
            acc  += __shfl_xor_sync(0xffffffffu, acc, off);
            msum += __shfl_xor_sync(0xffffffffu, msum, off);
        }
        if (lane == 0) {
            int seq_end = msum - 1;
            if (seq_end < 0) seq_end = 0;
            int l0 = lab_s[0];
            int llast = lab_s[seq_end];
            num_sh = st_s[l0] + e_s[l0] + acc + en_s[llast];
        }
    }

    __syncthreads();

    if (warp == 0) {
        const int j = (lane < TT) ? lane : (TT - 1);

        float q  = exp2f((st_s[j] + e_s[j]) * L2E);
        int   Eq = 0;

        for (int c = 0; c < NCH; c++) {
            float Ek[TT];
            #pragma unroll
            for (int k = 0; k < TT; k++) Ek[k] = E_s[c * TT + k];
            float Em = Ek[0];
            #pragma unroll
            for (int k = 1; k < TT; k++) Em = fmaxf(Em, Ek[k]);

            float s = 0.f;
            #pragma unroll
            for (int k = 0; k < TT; k++) {
                float pk = __shfl_sync(0xffffffffu, q, k);
                float d  = Ek[k] - Em;
                float sc = (d > -120.f)
                         ? __int_as_float((((int)d) + 127) << 23) : 0.f;
                s = fmaf(pk * sc, M_s[(c * TT + k) * TT + j], s);
            }
            q  = s;
            Eq += (int)Em;

            float q0 = __shfl_sync(0xffffffffu, q, 0);
            float q1 = __shfl_sync(0xffffffffu, q, 1);
            float q2 = __shfl_sync(0xffffffffu, q, 2);
            float q3 = __shfl_sync(0xffffffffu, q, 3);
            float q4 = __shfl_sync(0xffffffffu, q, 4);
            float q5 = __shfl_sync(0xffffffffu, q, 5);
            float q6 = __shfl_sync(0xffffffffu, q, 6);
            float q7 = __shfl_sync(0xffffffffu, q, 7);
            float q8 = __shfl_sync(0xffffffffu, q, 8);
            float qm = fmaxf(fmaxf(fmaxf(q0, q1), fmaxf(q2, q3)),
                             fmaxf(fmaxf(q4, q5), fmaxf(q6, q7)));
            qm = fmaxf(qm, q8);
            int ex = (__float_as_int(qm) >> 23) & 0xFF;
            float sc2 = __int_as_float((254 - ex) << 23);
            q  *= sc2;
            Eq += ex - 127;
        }

        float v = (lane < TT) ? q * exp2f(en_s[j] * L2E) : 0.f;
        #pragma unroll
        for (int off = 16; off > 0; off >>= 1)
            v += __shfl_xor_sync(0xffffffffu, v, off);
        float denom = LN2 * (__log2f(v) + (float)Eq);

        if (lane == 0) g_llh[b] = num_sh - denom;
    }
}

// ---------------------------------------------------------------------------
// Kernel C: loss = -mean(llh), deterministic tree reduce
// ---------------------------------------------------------------------------
__global__ void loss_kernel(float* __restrict__ loss_out)
{
    int lane = threadIdx.x;   // 32 threads
    float v = g_llh[lane] + g_llh[lane + 32];
    #pragma unroll
    for (int off = 16; off > 0; off >>= 1)
        v += __shfl_xor_sync(0xffffffffu, v, off);
    if (lane == 0) loss_out[0] = -v * (1.0f / (float)BB);
}

// ---------------------------------------------------------------------------
extern "C" void kernel_launch(void* const* d_in, const int* in_sizes, int n_in,
                              void* d_out, int out_size)
{
    const float* hidden      = (const float*)d_in[0];
    const int*   attn_mask   = (const int*)d_in[1];
    const int*   labels      = (const int*)d_in[2];   // int32 (JAX x64 disabled)
    const float* W           = (const float*)d_in[3];
    const float* bias        = (const float*)d_in[4];
    const float* start_trans = (const float*)d_in[5];
    const float* end_trans   = (const float*)d_in[6];
    const float* trans       = (const float*)d_in[7];

    float* out = (float*)d_out;

    static float* scratch = nullptr;
    if (!scratch) {
        void* p = nullptr;
        cudaGetSymbolAddress(&p, g_logits_scratch);
        scratch = (float*)p;
    }

    const int NLOG = BB * LL * TT;   // 294912
    float* loss_ptr;
    float* logits_ptr;
    if (out_size >= NLOG + 1) {          // (loss, logits) concatenated
        loss_ptr   = out;
        logits_ptr = out + 1;
    } else if (out_size == NLOG) {       // logits only
        loss_ptr   = scratch;
        logits_ptr = out;
    } else {                             // loss only
        loss_ptr   = out;
        logits_ptr = scratch;
    }

    logits_kernel<<<2048, 256>>>(hidden, W, bias, logits_ptr);
    crf_kernel<<<BB, 800>>>(logits_ptr, attn_mask, labels,
                            start_trans, end_trans, trans);
    loss_kernel<<<1, 32>>>(loss_ptr);
}

// round 9
// speedup vs baseline: 1.5141x; 1.0011x over previous
#include <cuda_runtime.h>
#include <cuda_bf16.h>
#include <math_constants.h>

// Problem constants (fixed shapes)
#define BB 64
#define LL 512
#define HH 768
#define TT 9
#define NROWS (BB * LL)

#define NCH 8        // chunks per sequence
#define CHLEN 64     // steps per chunk

__device__ float g_llh[BB];
__device__ float g_logits_scratch[BB * LL * TT];   // fallback if out has no room

// ---------------------------------------------------------------------------
// Kernel A: logits = hidden @ W + b
// ONE row-pair per warp (grid 2048 x 256 = 16384 warps = all row pairs).
// Full prefetch: all 12 float4 of the pair issued up front (6 KB in flight
// per warp), then 432 FMA + 216 LDS of compute (~1300 cyc) fully covers the
// 577-cyc DRAM latency. launch_bounds(256,2) caps regs at 128 (fits: 48 load
// regs + 18 acc + temps ~ 90).
// W in smem, swizzled Ws[9k + t + (k>>5)] -> conflict-free scalar LDS.
// ---------------------------------------------------------------------------
__global__ __launch_bounds__(256, 2) void logits_kernel(
    const float* __restrict__ hidden,
    const float* __restrict__ W,
    const float* __restrict__ bias,
    float* __restrict__ logits)
{
    __shared__ float Ws[HH * TT + (HH >> 5)];   // 6936 floats
    __shared__ float bs[TT];

    for (int i = threadIdx.x; i < HH * TT; i += 256) {
        int k = i / 9;
        int t = i - 9 * k;
        Ws[9 * k + t + (k >> 5)] = W[i];
    }
    if (threadIdx.x < TT) bs[threadIdx.x] = bias[threadIdx.x];
    __syncthreads();

    const int lane = threadIdx.x & 31;
    const int rp   = blockIdx.x * 8 + (threadIdx.x >> 5);   // row pair 0..16383

    const float4* h0 = (const float4*)(hidden + (size_t)(2 * rp) * HH);
    const float4* h1 = h0 + (HH / 4);

    // full prefetch: 12 LDG.128 in flight
    float4 a0[6], a1[6];
    #pragma unroll
    for (int it = 0; it < 6; it++) {
        a0[it] = h0[it * 32 + lane];
        a1[it] = h1[it * 32 + lane];
    }

    float acc0[TT], acc1[TT];
    #pragma unroll
    for (int t = 0; t < TT; t++) { acc0[t] = 0.f; acc1[t] = 0.f; }

    #pragma unroll
    for (int it = 0; it < 6; it++) {
        const int k4 = it * 32 + lane;
        const int wb = 36 * k4 + (k4 >> 3);
        const float hx0[4] = {a0[it].x, a0[it].y, a0[it].z, a0[it].w};
        const float hx1[4] = {a1[it].x, a1[it].y, a1[it].z, a1[it].w};
        #pragma unroll
        for (int kk = 0; kk < 4; kk++) {
            const float* wr = &Ws[wb + 9 * kk];
            const float h0v = hx0[kk];
            const float h1v = hx1[kk];
            #pragma unroll
            for (int t = 0; t < TT; t++) {
                const float w = wr[t];
                acc0[t] = fmaf(h0v, w, acc0[t]);
                acc1[t] = fmaf(h1v, w, acc1[t]);
            }
        }
    }

    // butterfly: every lane ends with the full sums
    #pragma unroll
    for (int t = 0; t < TT; t++) {
        #pragma unroll
        for (int off = 16; off > 0; off >>= 1) {
            acc0[t] += __shfl_xor_sync(0xffffffffu, acc0[t], off);
            acc1[t] += __shfl_xor_sync(0xffffffffu, acc1[t], off);
        }
    }

    float* o = logits + (size_t)(2 * rp) * TT;
    #pragma unroll
    for (int t = 0; t < TT; t++) {
        if (lane == t)      o[t]      = acc0[t] + bs[t];
        if (lane == 9 + t)  o[TT + t] = acc1[t] + bs[t];
    }
}

// ---------------------------------------------------------------------------
// Kernel B: per-batch CRF with CHUNKED parallel scan (unchanged — working).
// ---------------------------------------------------------------------------
__global__ __launch_bounds__(800) void crf_kernel(
    const float* __restrict__ logits,
    const int*   __restrict__ mask,
    const int*   __restrict__ labels,
    const float* __restrict__ start_trans,
    const float* __restrict__ end_trans,
    const float* __restrict__ trans)
{
    __shared__ float e_s[LL * TT];
    __shared__ float ee_s[LL * TT];
    __shared__ float m_s[LL];
    __shared__ int   lab_s[LL];
    __shared__ float tr_s[TT * TT];
    __shared__ float st_s[TT];
    __shared__ float en_s[TT];
    __shared__ float M_s[NCH * TT * TT];
    __shared__ float E_s[NCH * TT];
    __shared__ float num_sh;

    const int b    = blockIdx.x;
    const int tid  = threadIdx.x;
    const int lane = tid & 31;
    const int warp = tid >> 5;

    const float L2E = 1.4426950408889634f;
    const float LN2 = 0.6931471805599453f;

    const float* lg = logits + (size_t)b * LL * TT;
    #pragma unroll 2
    for (int i = tid; i < LL * TT; i += 800) {
        float e = lg[i];
        e_s[i]  = e;
        ee_s[i] = exp2f(e * L2E);
    }
    for (int i = tid; i < LL; i += 800) {
        int l = labels[(size_t)b * LL + i];
        lab_s[i] = (l == -100) ? 0 : l;
        m_s[i]   = (float)mask[(size_t)b * LL + i];
    }
    if (tid < TT * TT) tr_s[tid] = trans[tid];
    if (tid < TT) { st_s[tid] = start_trans[tid]; en_s[tid] = end_trans[tid]; }
    __syncthreads();

    if (warp < 24) {
        const int c  = warp / 3;
        const int rg = warp % 3;
        int r = lane / 9; if (r > 2) r = 2;
        const int j = lane % 9;
        const int i = rg * 3 + r;
        const int base = r * 9;

        float et[TT];
        #pragma unroll
        for (int k = 0; k < TT; k++) et[k] = exp2f(tr_s[k * TT + j] * L2E);

        float q = (j == i) ? 1.f : 0.f;
        int   E = 0;

        const int t0 = c * CHLEN + 1;
        int t1 = t0 + CHLEN; if (t1 > LL) t1 = LL;

        float eej_next = ee_s[t0 * TT + j];
        float ms_next  = m_s[t0];

        for (int t = t0; t < t1; t++) {
            const float eej = eej_next;
            const float ms  = ms_next;
            if (t + 1 < t1) {
                eej_next = ee_s[(t + 1) * TT + j];
                ms_next  = m_s[t + 1];
            }

            float p0 = __shfl_sync(0xffffffffu, q, base + 0);
            float p1 = __shfl_sync(0xffffffffu, q, base + 1);
            float p2 = __shfl_sync(0xffffffffu, q, base + 2);
            float p3 = __shfl_sync(0xffffffffu, q, base + 3);
            float p4 = __shfl_sync(0xffffffffu, q, base + 4);
            float p5 = __shfl_sync(0xffffffffu, q, base + 5);
            float p6 = __shfl_sync(0xffffffffu, q, base + 6);
            float p7 = __shfl_sync(0xffffffffu, q, base + 7);
            float p8 = __shfl_sync(0xffffffffu, q, base + 8);

            float a  = fmaf(p1, et[1], p0 * et[0]);  a  = fmaf(p2, et[2], a);
            float b2 = fmaf(p4, et[4], p3 * et[3]);  b2 = fmaf(p5, et[5], b2);
            float cc = fmaf(p7, et[7], p6 * et[6]);  cc = fmaf(p8, et[8], cc);
            float s  = ((a + b2) + cc) * eej;

            q = (ms != 0.f) ? s : q;

            if ((t & 7) == 7) {
                float pm = fmaxf(fmaxf(fmaxf(p0, p1), fmaxf(p2, p3)),
                                 fmaxf(fmaxf(p4, p5), fmaxf(p6, p7)));
                pm = fmaxf(pm, p8);
                int ex = (__float_as_int(pm) >> 23) & 0xFF;
                float sc = __int_as_float((254 - ex) << 23);
                q *= sc;
                E += ex - 127;
            }
        }

        if (lane < 27) {
            M_s[(c * TT + i) * TT + j] = q;
            if (j == 0) E_s[c * TT + i] = (float)E;
        }
    } else {
        float acc = 0.f;
        int   msum = 0;
        for (int t = lane; t < LL; t += 32) {
            msum += (m_s[t] != 0.f) ? 1 : 0;
            if (t >= 1) {
                int lp = lab_s[t - 1], lt = lab_s[t];
                acc = fmaf(tr_s[lp * TT + lt] + e_s[t * TT + lt], m_s[t], acc);
            }
        }
        #pragma unroll
        for (int off = 16; off > 0; off >>= 1) {
            acc  += __shfl_xor_sync(0xffffffffu, acc, off);
            msum += __shfl_xor_sync(0xffffffffu, msum, off);
        }
        if (lane == 0) {
            int seq_end = msum - 1;
            if (seq_end < 0) seq_end = 0;
            int l0 = lab_s[0];
            int llast = lab_s[seq_end];
            num_sh = st_s[l0] + e_s[l0] + acc + en_s[llast];
        }
    }

    __syncthreads();

    if (warp == 0) {
        const int j = (lane < TT) ? lane : (TT - 1);

        float q  = exp2f((st_s[j] + e_s[j]) * L2E);
        int   Eq = 0;

        for (int c = 0; c < NCH; c++) {
            float Ek[TT];
            #pragma unroll
            for (int k = 0; k < TT; k++) Ek[k] = E_s[c * TT + k];
            float Em = Ek[0];
            #pragma unroll
            for (int k = 1; k < TT; k++) Em = fmaxf(Em, Ek[k]);

            float s = 0.f;
            #pragma unroll
            for (int k = 0; k < TT; k++) {
                float pk = __shfl_sync(0xffffffffu, q, k);
                float d  = Ek[k] - Em;
                float sc = (d > -120.f)
                         ? __int_as_float((((int)d) + 127) << 23) : 0.f;
                s = fmaf(pk * sc, M_s[(c * TT + k) * TT + j], s);
            }
            q  = s;
            Eq += (int)Em;

            float q0 = __shfl_sync(0xffffffffu, q, 0);
            float q1 = __shfl_sync(0xffffffffu, q, 1);
            float q2 = __shfl_sync(0xffffffffu, q, 2);
            float q3 = __shfl_sync(0xffffffffu, q, 3);
            float q4 = __shfl_sync(0xffffffffu, q, 4);
            float q5 = __shfl_sync(0xffffffffu, q, 5);
            float q6 = __shfl_sync(0xffffffffu, q, 6);
            float q7 = __shfl_sync(0xffffffffu, q, 7);
            float q8 = __shfl_sync(0xffffffffu, q, 8);
            float qm = fmaxf(fmaxf(fmaxf(q0, q1), fmaxf(q2, q3)),
                             fmaxf(fmaxf(q4, q5), fmaxf(q6, q7)));
            qm = fmaxf(qm, q8);
            int ex = (__float_as_int(qm) >> 23) & 0xFF;
            float sc2 = __int_as_float((254 - ex) << 23);
            q  *= sc2;
            Eq += ex - 127;
        }

        float v = (lane < TT) ? q * exp2f(en_s[j] * L2E) : 0.f;
        #pragma unroll
        for (int off = 16; off > 0; off >>= 1)
            v += __shfl_xor_sync(0xffffffffu, v, off);
        float denom = LN2 * (__log2f(v) + (float)Eq);

        if (lane == 0) g_llh[b] = num_sh - denom;
    }
}

// ---------------------------------------------------------------------------
// Kernel C: loss = -mean(llh), deterministic tree reduce
// ---------------------------------------------------------------------------
__global__ void loss_kernel(float* __restrict__ loss_out)
{
    int lane = threadIdx.x;   // 32 threads
    float v = g_llh[lane] + g_llh[lane + 32];
    #pragma unroll
    for (int off = 16; off > 0; off >>= 1)
        v += __shfl_xor_sync(0xffffffffu, v, off);
    if (lane == 0) loss_out[0] = -v * (1.0f / (float)BB);
}

// ---------------------------------------------------------------------------
extern "C" void kernel_launch(void* const* d_in, const int* in_sizes, int n_in,
                              void* d_out, int out_size)
{
    const float* hidden      = (const float*)d_in[0];
    const int*   attn_mask   = (const int*)d_in[1];
    const int*   labels      = (const int*)d_in[2];   // int32 (JAX x64 disabled)
    const float* W           = (const float*)d_in[3];
    const float* bias        = (const float*)d_in[4];
    const float* start_trans = (const float*)d_in[5];
    const float* end_trans   = (const float*)d_in[6];
    const float* trans       = (const float*)d_in[7];

    float* out = (float*)d_out;

    static float* scratch = nullptr;
    if (!scratch) {
        void* p = nullptr;
        cudaGetSymbolAddress(&p, g_logits_scratch);
        scratch = (float*)p;
    }

    const int NLOG = BB * LL * TT;   // 294912
    float* loss_ptr;
    float* logits_ptr;
    if (out_size >= NLOG + 1) {          // (loss, logits) concatenated
        loss_ptr   = out;
        logits_ptr = out + 1;
    } else if (out_size == NLOG) {       // logits only
        loss_ptr   = scratch;
        logits_ptr = out;
    } else {                             // loss only
        loss_ptr   = out;
        logits_ptr = scratch;
    }

    logits_kernel<<<2048, 256>>>(hidden, W, bias, logits_ptr);
    crf_kernel<<<BB, 800>>>(logits_ptr, attn_mask, labels,
                            start_trans, end_trans, trans);
    loss_kernel<<<1, 32>>>(loss_ptr);
}